// round 14
// baseline (speedup 1.0000x reference)
#include <cuda_runtime.h>
#include <cuda_fp16.h>
#include <cstdint>

#define N_VOX 200000
#define NFW 128
#define SC 136                       // C staging row stride (floats)
#define SMEM_BYTES (256 * SC * 4)    // 139264 B (>= K*256*4 idx slab; unioned)
#define CTHREADS 512                 // 16 warps: 8m x 2n of m32 x n64

// ---------------- scratch (static device globals; no allocation) ----------------
__device__ __half g_a[(size_t)N_VOX * 128];  // f16 k-permuted activations
__device__ float g_h[(size_t)N_VOX * 128];   // conv1 output h (f32 natural)
__device__ float g_h2[(size_t)N_VOX * 128];  // idconv + conv2 output (f32 natural)
__device__ float g_stats[384];
__device__ float g_tp[16 * 256];
__device__ __half g_wt[802816];              // fragment-major f16 weights

#define WT1_OFF 0
#define WT2_OFF (27 * 128 * 64)
#define WTD_OFF (WT2_OFF + 27 * 128 * 128)
#define WTID_OFF (WTD_OFF + 8 * 128 * 128)

// A permutation within each 64-half chunk: for group-pair gp (groups 2gp,2gp+1),
// lane lp owns one 16B run at pos = gp*32 + lp*8 containing
// [g_even: {2lp,2lp+1,2lp+8,2lp+9}, g_odd: same] -> one LDG.128 = 2 groups' a-frags.
//
// W fragment-major superblocks of 256 halves: per (k,ch), superblock sb = jg*2+gp;
// within: off = lane*8 + gg*4 + slot.

// ---------------- helpers ----------------
__device__ __forceinline__ float silu_(float z) {
    return z * (1.f / (1.f + __expf(-z)));
}
__device__ __forceinline__ void mma16(float* c, const uint32_t* a, uint32_t b0, uint32_t b1) {
    asm volatile(
        "mma.sync.aligned.m16n8k16.row.col.f32.f16.f16.f32 "
        "{%0,%1,%2,%3}, {%4,%5,%6,%7}, {%8,%9}, {%0,%1,%2,%3};"
        : "+f"(c[0]), "+f"(c[1]), "+f"(c[2]), "+f"(c[3])
        : "r"(a[0]), "r"(a[1]), "r"(a[2]), "r"(a[3]), "r"(b0), "r"(b1));
}
__device__ __forceinline__ int permpos64(int c6) {
    int g = c6 >> 4, h = c6 & 15;
    int lp = (h >> 1) & 3, hi = h >> 3, e = h & 1;
    return ((g >> 1) << 5) | (lp << 3) | ((g & 1) << 2) | (hi << 1) | e;
}

// ---------------- small kernels ----------------
template <int C>
__global__ void stats_kernel(const float* __restrict__ X, int M,
                             float* __restrict__ gsum, float* __restrict__ gsq) {
    constexpr int RPB = 256 / C;
    const int c = threadIdx.x & (C - 1);
    const int rg = threadIdx.x / C;
    float s = 0.f, q = 0.f;
    for (int r = blockIdx.x * RPB + rg; r < M; r += gridDim.x * RPB) {
        float v = X[(size_t)r * C + c];
        s += v;
        q += v * v;
    }
    __shared__ float sh[256];
    __shared__ float sh2[256];
    sh[threadIdx.x] = s;
    sh2[threadIdx.x] = q;
    __syncthreads();
    if (threadIdx.x < C) {
        #pragma unroll
        for (int g = 1; g < RPB; ++g) {
            s += sh[g * C + c];
            q += sh2[g * C + c];
        }
        atomicAdd(&gsum[c], s);
        atomicAdd(&gsq[c], q);
    }
}

// bnsilu with fused BN-finalize; output f16 k-permuted (64-half chunks)
template <int C>
__global__ void bnsilu_kernel(const float* __restrict__ X,
                              const float* __restrict__ gsum, const float* __restrict__ gsq,
                              const float* __restrict__ g, const float* __restrict__ be,
                              float invM, size_t total, __half* __restrict__ out) {
    __shared__ float ssc[C], sbi[C];
    if (threadIdx.x < C) {
        int c = threadIdx.x;
        float m = gsum[c] * invM;
        float v = gsq[c] * invM - m * m;
        float a = g[c] * rsqrtf(v + 1e-5f);
        ssc[c] = a;
        sbi[c] = be[c] - m * a;
    }
    __syncthreads();
    for (size_t i = (size_t)blockIdx.x * blockDim.x + threadIdx.x; i < total;
         i += (size_t)gridDim.x * blockDim.x) {
        int c = (int)(i & (size_t)(C - 1));
        float z = X[i] * ssc[c] + sbi[c];
        int pos = permpos64((int)(i & 63));
        out[(i & ~(size_t)63) | (size_t)pos] = __float2half_rn(silu_(z));
    }
}

// f32 natural -> f16 k-permuted (64-half chunks)
__global__ void tohalf_kernel(const float* __restrict__ X, size_t total,
                              __half* __restrict__ out) {
    for (size_t i = (size_t)blockIdx.x * blockDim.x + threadIdx.x; i < total;
         i += (size_t)gridDim.x * blockDim.x) {
        int pos = permpos64((int)(i & 63));
        out[(i & ~(size_t)63) | (size_t)pos] = __float2half_rn(X[i]);
    }
}

// W[k][c][n] -> fragment-major superblocks. block 0 zeroes stats; tail blocks temb.
__global__ void transpose_w_kernel(const float* __restrict__ W, __half* __restrict__ Wt,
                                   int K, int CIN, float* stats_zero,
                                   const float* __restrict__ t, const float* __restrict__ Wtm,
                                   const float* __restrict__ bt, float* __restrict__ tp,
                                   int ntb) {
    if (ntb > 0 && (int)blockIdx.x >= (int)gridDim.x - ntb) {
        __shared__ float st[256];
        const int b = blockIdx.x - (gridDim.x - ntb);
        const int j = threadIdx.x;
        st[j] = silu_(t[b * 256 + j]);
        __syncthreads();
        float acc = bt[j];
        #pragma unroll 8
        for (int e = 0; e < 256; ++e) acc += st[e] * Wtm[e * 256 + j];
        tp[b * 256 + j] = acc;
        return;
    }
    if (stats_zero && blockIdx.x == 0) {
        for (int z = threadIdx.x; z < 384; z += blockDim.x) stats_zero[z] = 0.f;
    }
    const int nwb = gridDim.x - ntb;
    const int hpk = CIN * 128;          // halves per k
    const int total = K * hpk;
    for (int i = blockIdx.x * blockDim.x + threadIdx.x; i < total;
         i += nwb * blockDim.x) {
        int k = i / hpk;
        int rem = i - k * hpk;
        int sblk = rem >> 8;            // 256-half superblocks
        int off = rem & 255;
        int ch = sblk >> 5;             // superblock / 32
        int sb = sblk & 31;
        int jg = sb >> 1, gp = sb & 1;
        int lane = off >> 3, gg = (off >> 2) & 1, slot = off & 3;
        int lr = lane >> 2, lp = lane & 3;
        int g = gp * 2 + gg;
        int hi = slot >> 1, e = slot & 1;
        int c = (ch << 6) | (g << 4) | (2 * lp + 8 * hi + e);
        int n = (jg << 3) | lr;
        Wt[i] = __float2half_rn(W[(k * CIN + c) * 128 + n]);
    }
}

// ---------------- direct-LDG.128 f16 m16n8k16 gathered sparse-conv GEMM ----------------
// 256-row x 128-col tile, 512 threads (16 warps = 8m x 2n of m32 x n64), f32 accum.
// nbr indices pre-staged to smem (removes DRAM-latency from the mainloop chain).
// MODE 0: + bias (+bias2); MODE 1: TE affine; MODE 2: + addend (f32)
template <int CIN, int MODE, bool IDENT>
__global__ void __launch_bounds__(CTHREADS, 1)
conv_mma(const __half* __restrict__ Af, const int* __restrict__ nbr, int K, int M,
         const __half* __restrict__ Wt,
         const float* __restrict__ bias, const float* __restrict__ bias2,
         float* __restrict__ out, const float* __restrict__ addend,
         const float* __restrict__ tp, const int* __restrict__ b_idx) {
    extern __shared__ char smraw[];
    float* Cs = (float*)smraw;          // epilogue staging (after mainloop)
    int* Sidx = (int*)smraw;            // idx slab K x 256 (mainloop only)

    const int tid = threadIdx.x;
    const int wid = tid >> 5, lane = tid & 31;
    const int wr = wid & 7, wc = wid >> 3;   // m0=32*wr, n0=64*wc
    const int lr = lane >> 2, lp = lane & 3;
    const int tile = blockIdx.x * 256;

    constexpr int NCH = CIN / 64;
    const int NC = K * NCH;

    // ---- stage all neighbor indices for this tile into smem (coalesced, high MLP)
    if (!IDENT) {
        const int tot = K << 8;
        for (int i = tid; i < tot; i += CTHREADS) {
            int k = i >> 8, r = i & 255;
            int row = tile + r;
            Sidx[i] = (row < M) ? __ldg(nbr + (size_t)k * M + row) : -1;
        }
        __syncthreads();
    }

    float acc[2][8][4];
    #pragma unroll
    for (int t = 0; t < 2; ++t)
        #pragma unroll
        for (int j = 0; j < 8; ++j)
            #pragma unroll
            for (int i = 0; i < 4; ++i) acc[t][j][i] = 0.f;

    const int rq = 32 * wr + lr;        // warp-local row base (quads at +8)

    for (int ci = 0; ci < NC; ++ci) {
        const int k = (NCH == 1) ? ci : (ci >> 1);
        const int ch = (NCH == 1) ? 0 : (ci & 1);

        int idxs[4];
        #pragma unroll
        for (int q = 0; q < 4; ++q) {
            if (IDENT) {
                int row = tile + rq + 8 * q;
                idxs[q] = (row < M) ? row : -1;
            } else {
                idxs[q] = Sidx[(k << 8) + rq + 8 * q];
            }
        }
        const __half* aq[4];
        #pragma unroll
        for (int q = 0; q < 4; ++q)
            aq[q] = Af + (size_t)(idxs[q] < 0 ? 0 : idxs[q]) * CIN + ch * 64 + lp * 8;

        const __half* wb = Wt + ((size_t)(k * NCH + ch) * 32 + (size_t)wc * 16) * 256
                              + lane * 8;

        #pragma unroll
        for (int gp = 0; gp < 2; ++gp) {
            uint4 al[4];
            #pragma unroll
            for (int q = 0; q < 4; ++q) {
                uint4 v = make_uint4(0u, 0u, 0u, 0u);
                if (idxs[q] >= 0) v = *(const uint4*)(aq[q] + gp * 32);
                al[q] = v;
            }
            uint32_t a0[2][4], a1[2][4];
            #pragma unroll
            for (int t = 0; t < 2; ++t) {
                a0[t][0] = al[2 * t].x;     a0[t][1] = al[2 * t + 1].x;
                a0[t][2] = al[2 * t].y;     a0[t][3] = al[2 * t + 1].y;
                a1[t][0] = al[2 * t].z;     a1[t][1] = al[2 * t + 1].z;
                a1[t][2] = al[2 * t].w;     a1[t][3] = al[2 * t + 1].w;
            }
            #pragma unroll
            for (int j = 0; j < 8; ++j) {
                uint4 b = *(const uint4*)(wb + (size_t)(j * 2 + gp) * 256);
                mma16(acc[0][j], a0[0], b.x, b.y);
                mma16(acc[1][j], a0[1], b.x, b.y);
                mma16(acc[0][j], a1[0], b.z, b.w);
                mma16(acc[1][j], a1[1], b.z, b.w);
            }
        }
    }

    // ---- stage C through smem for coalesced stores ----
    __syncthreads();
    #pragma unroll
    for (int t = 0; t < 2; ++t)
        #pragma unroll
        for (int j = 0; j < 8; ++j) {
            int r0 = 32 * wr + 16 * t + lr;
            int cc0 = 64 * wc + 8 * j + 2 * lp;
            *(float2*)&Cs[r0 * SC + cc0] = make_float2(acc[t][j][0], acc[t][j][1]);
            *(float2*)&Cs[(r0 + 8) * SC + cc0] = make_float2(acc[t][j][2], acc[t][j][3]);
        }
    __syncthreads();

    // ---- epilogue: thread -> (row, half) ----
    const int r = tid >> 1;
    const int hf = tid & 1;
    const int row = tile + r;
    if (row < M) {
        const float* tpr = nullptr;
        if (MODE == 1) tpr = tp + b_idx[row] * 256;
        #pragma unroll 4
        for (int q = 0; q < 16; ++q) {
            const int p0 = hf * 64 + q * 4;
            float v[4];
            #pragma unroll
            for (int i = 0; i < 4; ++i) v[i] = Cs[r * SC + p0 + i];
            float4 ad;
            if (MODE == 2) ad = *(const float4*)(addend + (size_t)row * NFW + p0);
            #pragma unroll
            for (int i = 0; i < 4; ++i) {
                if (MODE == 0) {
                    if (bias) v[i] += bias[p0 + i];
                    if (bias2) v[i] += bias2[p0 + i];
                } else if (MODE == 1) {
                    v[i] = (1.f + tpr[p0 + i]) * (v[i] + bias[p0 + i]) + tpr[128 + p0 + i];
                } else {
                    v[i] += (&ad.x)[i];
                }
            }
            *(float4*)(out + (size_t)row * NFW + p0) = make_float4(v[0], v[1], v[2], v[3]);
        }
    }
}

// ---------------- launch ----------------
extern "C" void kernel_launch(void* const* d_in, const int* in_sizes, int n_in,
                              void* d_out, int out_size) {
    const float* x        = (const float*)d_in[0];
    const float* t        = (const float*)d_in[1];
    const int*   b_idx    = (const int*)d_in[2];
    const int*   nbr      = (const int*)d_in[3];
    const int*   nbr_down = (const int*)d_in[4];
    const float* g1       = (const float*)d_in[5];
    const float* be1      = (const float*)d_in[6];
    const float* W1       = (const float*)d_in[7];
    const float* b1       = (const float*)d_in[8];
    const float* Wtm      = (const float*)d_in[9];
    const float* bt       = (const float*)d_in[10];
    const float* g2       = (const float*)d_in[11];
    const float* be2      = (const float*)d_in[12];
    const float* W2       = (const float*)d_in[13];
    const float* b2       = (const float*)d_in[14];
    const float* Wid      = (const float*)d_in[15];
    const float* bid      = (const float*)d_in[16];
    const float* Wd       = (const float*)d_in[17];
    float* out = (float*)d_out;

    float *ph, *ph2, *pstats, *ptp;
    __half *pa, *pwt;
    cudaGetSymbolAddress((void**)&pa, g_a);
    cudaGetSymbolAddress((void**)&ph, g_h);
    cudaGetSymbolAddress((void**)&ph2, g_h2);
    cudaGetSymbolAddress((void**)&pstats, g_stats);
    cudaGetSymbolAddress((void**)&ptp, g_tp);
    cudaGetSymbolAddress((void**)&pwt, g_wt);

    cudaFuncSetAttribute(conv_mma<64, 1, false>,
                         cudaFuncAttributeMaxDynamicSharedMemorySize, SMEM_BYTES);
    cudaFuncSetAttribute(conv_mma<64, 0, true>,
                         cudaFuncAttributeMaxDynamicSharedMemorySize, SMEM_BYTES);
    cudaFuncSetAttribute(conv_mma<128, 2, false>,
                         cudaFuncAttributeMaxDynamicSharedMemorySize, SMEM_BYTES);
    cudaFuncSetAttribute(conv_mma<128, 0, false>,
                         cudaFuncAttributeMaxDynamicSharedMemorySize, SMEM_BYTES);

    const int N = in_sizes[0] / 64;             // 200000
    const int K = in_sizes[3] / N;              // 27
    const int KD = in_sizes[17] / (128 * 128);  // 8
    const int ND = in_sizes[4] / KD;            // 25000
    const float invN = 1.f / (float)N;
    const int GN = (N + 255) / 256;
    const int GD = (ND + 255) / 256;
    __half* pxh = pa + (size_t)N * 64;          // f16-permuted x (second half of g_a)

    // Launch order: conv1 at launch #4 (the ncu-captured slot).
    // 1: W1 transpose (fragment-major) + zero stats + temb (16 tail blocks)
    transpose_w_kernel<<<232, 256>>>(W1, pwt + WT1_OFF, K, 64, pstats, t, Wtm, bt, ptp, 16);
    // 2: BN1 stats
    stats_kernel<64><<<512, 256>>>(x, N, pstats + 0, pstats + 64);
    // 3: bnsilu1 (fused finalize) -> g_a[0:N*64]
    bnsilu_kernel<64><<<2048, 256>>>(x, pstats + 0, pstats + 64, g1, be1, invN,
                                     (size_t)N * 64, pa);
    // 4: conv1 (64->128) + b1 + TE affine -> g_h   << ncu capture slot
    conv_mma<64, 1, false><<<GN, CTHREADS, SMEM_BYTES>>>(
        pa, nbr, K, N, pwt + WT1_OFF, b1, nullptr, ph, nullptr, ptp, b_idx);

    // 5: x -> f16 permuted (for idconv)
    tohalf_kernel<<<2048, 256>>>(x, (size_t)N * 64, pxh);
    // 6: W2 transpose
    transpose_w_kernel<<<432, 256>>>(W2, pwt + WT2_OFF, K, 128, nullptr,
                                     nullptr, nullptr, nullptr, nullptr, 0);
    // 7: BN2 stats
    stats_kernel<128><<<512, 256>>>(ph, N, pstats + 128, pstats + 256);
    // 8: Wid transpose
    transpose_w_kernel<<<32, 256>>>(Wid, pwt + WTID_OFF, 1, 64, nullptr,
                                    nullptr, nullptr, nullptr, nullptr, 0);
    // 9: idconv: h2 = x @ Wid + bid + b2
    conv_mma<64, 0, true><<<GN, CTHREADS, SMEM_BYTES>>>(
        pxh, nullptr, 1, N, pwt + WTID_OFF, bid, b2, ph2, nullptr, nullptr, nullptr);
    // 10: bnsilu2 (fused finalize) -> g_a (full N*128)
    bnsilu_kernel<128><<<2048, 256>>>(ph, pstats + 128, pstats + 256, g2, be2, invN,
                                      (size_t)N * 128, pa);
    // 11: conv2 (128->128) + h2 addend -> g_h2
    conv_mma<128, 2, false><<<GN, CTHREADS, SMEM_BYTES>>>(
        pa, nbr, K, N, pwt + WT2_OFF, nullptr, nullptr, ph2, ph2, nullptr, nullptr);
    // 12: Wd transpose
    transpose_w_kernel<<<128, 256>>>(Wd, pwt + WTD_OFF, KD, 128, nullptr,
                                     nullptr, nullptr, nullptr, nullptr, 0);
    // 13: h2 -> f16 permuted
    tohalf_kernel<<<2048, 256>>>(ph2, (size_t)N * 128, pa);
    // 14: strided down conv (8 taps) -> out [ND, 128]
    conv_mma<128, 0, false><<<GD, CTHREADS, SMEM_BYTES>>>(
        pa, nbr_down, KD, ND, pwt + WTD_OFF, nullptr, nullptr, out,
        nullptr, nullptr, nullptr);
}

// round 15
// speedup vs baseline: 1.3908x; 1.3908x over previous
#include <cuda_runtime.h>
#include <cuda_fp16.h>
#include <cstdint>

#define N_VOX 200000
#define NFW 128
#define SC 136                       // C staging row stride (floats)
#define SMEM_BYTES (128 * SC * 4)    // 69632 B (epilogue staging only)
#define CTHREADS 256                 // 8 warps: 4m x 2n of m32 x n64; 2 CTAs/SM

// ---------------- scratch (static device globals; no allocation) ----------------
__device__ __half g_a[(size_t)N_VOX * 128];  // f16 k-permuted activations
__device__ float g_h[(size_t)N_VOX * 128];   // conv1 output h (f32 natural)
__device__ float g_h2[(size_t)N_VOX * 128];  // idconv + conv2 output (f32 natural)
__device__ float g_stats[384];
__device__ float g_tp[16 * 256];
__device__ __half g_wt[802816];              // fragment-major f16 weights

#define WT1_OFF 0
#define WT2_OFF (27 * 128 * 64)
#define WTD_OFF (WT2_OFF + 27 * 128 * 128)
#define WTID_OFF (WTD_OFF + 8 * 128 * 128)

// A permutation within each 64-half chunk: for group-pair gp (groups 2gp,2gp+1),
// lane lp owns one 16B run at pos = gp*32 + lp*8 containing
// [g_even: {2lp,2lp+1,2lp+8,2lp+9}, g_odd: same] -> one LDG.128 = 2 groups' a-frags.
//
// W fragment-major superblocks of 256 halves: per (k,ch), superblock sb = jg*2+gp;
// within: off = lane*8 + gg*4 + slot.

// ---------------- helpers ----------------
__device__ __forceinline__ float silu_(float z) {
    return z * (1.f / (1.f + __expf(-z)));
}
__device__ __forceinline__ void mma16(float* c, const uint32_t* a, uint32_t b0, uint32_t b1) {
    asm volatile(
        "mma.sync.aligned.m16n8k16.row.col.f32.f16.f16.f32 "
        "{%0,%1,%2,%3}, {%4,%5,%6,%7}, {%8,%9}, {%0,%1,%2,%3};"
        : "+f"(c[0]), "+f"(c[1]), "+f"(c[2]), "+f"(c[3])
        : "r"(a[0]), "r"(a[1]), "r"(a[2]), "r"(a[3]), "r"(b0), "r"(b1));
}
__device__ __forceinline__ int permpos64(int c6) {
    int g = c6 >> 4, h = c6 & 15;
    int lp = (h >> 1) & 3, hi = h >> 3, e = h & 1;
    return ((g >> 1) << 5) | (lp << 3) | ((g & 1) << 2) | (hi << 1) | e;
}

// ---------------- small kernels ----------------
template <int C>
__global__ void stats_kernel(const float* __restrict__ X, int M,
                             float* __restrict__ gsum, float* __restrict__ gsq) {
    constexpr int RPB = 256 / C;
    const int c = threadIdx.x & (C - 1);
    const int rg = threadIdx.x / C;
    float s = 0.f, q = 0.f;
    for (int r = blockIdx.x * RPB + rg; r < M; r += gridDim.x * RPB) {
        float v = X[(size_t)r * C + c];
        s += v;
        q += v * v;
    }
    __shared__ float sh[256];
    __shared__ float sh2[256];
    sh[threadIdx.x] = s;
    sh2[threadIdx.x] = q;
    __syncthreads();
    if (threadIdx.x < C) {
        #pragma unroll
        for (int g = 1; g < RPB; ++g) {
            s += sh[g * C + c];
            q += sh2[g * C + c];
        }
        atomicAdd(&gsum[c], s);
        atomicAdd(&gsq[c], q);
    }
}

// bnsilu with fused BN-finalize; output f16 k-permuted (64-half chunks)
template <int C>
__global__ void bnsilu_kernel(const float* __restrict__ X,
                              const float* __restrict__ gsum, const float* __restrict__ gsq,
                              const float* __restrict__ g, const float* __restrict__ be,
                              float invM, size_t total, __half* __restrict__ out) {
    __shared__ float ssc[C], sbi[C];
    if (threadIdx.x < C) {
        int c = threadIdx.x;
        float m = gsum[c] * invM;
        float v = gsq[c] * invM - m * m;
        float a = g[c] * rsqrtf(v + 1e-5f);
        ssc[c] = a;
        sbi[c] = be[c] - m * a;
    }
    __syncthreads();
    for (size_t i = (size_t)blockIdx.x * blockDim.x + threadIdx.x; i < total;
         i += (size_t)gridDim.x * blockDim.x) {
        int c = (int)(i & (size_t)(C - 1));
        float z = X[i] * ssc[c] + sbi[c];
        int pos = permpos64((int)(i & 63));
        out[(i & ~(size_t)63) | (size_t)pos] = __float2half_rn(silu_(z));
    }
}

// f32 natural -> f16 k-permuted (64-half chunks)
__global__ void tohalf_kernel(const float* __restrict__ X, size_t total,
                              __half* __restrict__ out) {
    for (size_t i = (size_t)blockIdx.x * blockDim.x + threadIdx.x; i < total;
         i += (size_t)gridDim.x * blockDim.x) {
        int pos = permpos64((int)(i & 63));
        out[(i & ~(size_t)63) | (size_t)pos] = __float2half_rn(X[i]);
    }
}

// W[k][c][n] -> fragment-major superblocks. block 0 zeroes stats; tail blocks temb.
__global__ void transpose_w_kernel(const float* __restrict__ W, __half* __restrict__ Wt,
                                   int K, int CIN, float* stats_zero,
                                   const float* __restrict__ t, const float* __restrict__ Wtm,
                                   const float* __restrict__ bt, float* __restrict__ tp,
                                   int ntb) {
    if (ntb > 0 && (int)blockIdx.x >= (int)gridDim.x - ntb) {
        __shared__ float st[256];
        const int b = blockIdx.x - (gridDim.x - ntb);
        const int j = threadIdx.x;
        st[j] = silu_(t[b * 256 + j]);
        __syncthreads();
        float acc = bt[j];
        #pragma unroll 8
        for (int e = 0; e < 256; ++e) acc += st[e] * Wtm[e * 256 + j];
        tp[b * 256 + j] = acc;
        return;
    }
    if (stats_zero && blockIdx.x == 0) {
        for (int z = threadIdx.x; z < 384; z += blockDim.x) stats_zero[z] = 0.f;
    }
    const int nwb = gridDim.x - ntb;
    const int hpk = CIN * 128;          // halves per k
    const int total = K * hpk;
    for (int i = blockIdx.x * blockDim.x + threadIdx.x; i < total;
         i += nwb * blockDim.x) {
        int k = i / hpk;
        int rem = i - k * hpk;
        int sblk = rem >> 8;            // 256-half superblocks
        int off = rem & 255;
        int ch = sblk >> 5;             // superblock / 32
        int sb = sblk & 31;
        int jg = sb >> 1, gp = sb & 1;
        int lane = off >> 3, gg = (off >> 2) & 1, slot = off & 3;
        int lr = lane >> 2, lp = lane & 3;
        int g = gp * 2 + gg;
        int hi = slot >> 1, e = slot & 1;
        int c = (ch << 6) | (g << 4) | (2 * lp + 8 * hi + e);
        int n = (jg << 3) | lr;
        Wt[i] = __float2half_rn(W[(k * CIN + c) * 128 + n]);
    }
}

// ---------------- direct-LDG.128 f16 m16n8k16 gathered sparse-conv GEMM ----------------
// 128-row x 128-col tile, 256 threads (8 warps = 4m x 2n of m32 x n64), f32 accum.
// 2 CTAs/SM (no shared barriers between them) hide gather latency via overlap.
// MODE 0: + bias (+bias2); MODE 1: TE affine; MODE 2: + addend (f32)
template <int CIN, int MODE, bool IDENT>
__global__ void __launch_bounds__(CTHREADS, 2)
conv_mma(const __half* __restrict__ Af, const int* __restrict__ nbr, int K, int M,
         const __half* __restrict__ Wt,
         const float* __restrict__ bias, const float* __restrict__ bias2,
         float* __restrict__ out, const float* __restrict__ addend,
         const float* __restrict__ tp, const int* __restrict__ b_idx) {
    extern __shared__ float Cs[];

    const int tid = threadIdx.x;
    const int wid = tid >> 5, lane = tid & 31;
    const int wr = wid & 3, wc = wid >> 2;   // m0=32*wr, n0=64*wc
    const int lr = lane >> 2, lp = lane & 3;
    const int tile = blockIdx.x * 128;

    constexpr int NCH = CIN / 64;
    const int NC = K * NCH;

    float acc[2][8][4];
    #pragma unroll
    for (int t = 0; t < 2; ++t)
        #pragma unroll
        for (int j = 0; j < 8; ++j)
            #pragma unroll
            for (int i = 0; i < 4; ++i) acc[t][j][i] = 0.f;

    const int rbase = tile + 32 * wr + lr;

    for (int ci = 0; ci < NC; ++ci) {
        const int k = (NCH == 1) ? ci : (ci >> 1);
        const int ch = (NCH == 1) ? 0 : (ci & 1);

        int idxs[4];
        #pragma unroll
        for (int q = 0; q < 4; ++q) {
            int row = rbase + 8 * q;
            idxs[q] = (row < M) ? (IDENT ? row : __ldg(nbr + (size_t)k * M + row)) : -1;
        }
        const __half* aq[4];
        #pragma unroll
        for (int q = 0; q < 4; ++q)
            aq[q] = Af + (size_t)(idxs[q] < 0 ? 0 : idxs[q]) * CIN + ch * 64 + lp * 8;

        const __half* wb = Wt + ((size_t)(k * NCH + ch) * 32 + (size_t)wc * 16) * 256
                              + lane * 8;

        #pragma unroll
        for (int gp = 0; gp < 2; ++gp) {
            uint4 al[4];
            #pragma unroll
            for (int q = 0; q < 4; ++q) {
                uint4 v = make_uint4(0u, 0u, 0u, 0u);
                if (idxs[q] >= 0) v = *(const uint4*)(aq[q] + gp * 32);
                al[q] = v;
            }
            uint32_t a0[2][4], a1[2][4];
            #pragma unroll
            for (int t = 0; t < 2; ++t) {
                a0[t][0] = al[2 * t].x;     a0[t][1] = al[2 * t + 1].x;
                a0[t][2] = al[2 * t].y;     a0[t][3] = al[2 * t + 1].y;
                a1[t][0] = al[2 * t].z;     a1[t][1] = al[2 * t + 1].z;
                a1[t][2] = al[2 * t].w;     a1[t][3] = al[2 * t + 1].w;
            }
            #pragma unroll
            for (int j = 0; j < 8; ++j) {
                uint4 b = *(const uint4*)(wb + (size_t)(j * 2 + gp) * 256);
                mma16(acc[0][j], a0[0], b.x, b.y);
                mma16(acc[1][j], a0[1], b.x, b.y);
                mma16(acc[0][j], a1[0], b.z, b.w);
                mma16(acc[1][j], a1[1], b.z, b.w);
            }
        }
    }

    // ---- stage C through smem for coalesced stores ----
    __syncthreads();
    #pragma unroll
    for (int t = 0; t < 2; ++t)
        #pragma unroll
        for (int j = 0; j < 8; ++j) {
            int r0 = 32 * wr + 16 * t + lr;
            int cc0 = 64 * wc + 8 * j + 2 * lp;
            *(float2*)&Cs[r0 * SC + cc0] = make_float2(acc[t][j][0], acc[t][j][1]);
            *(float2*)&Cs[(r0 + 8) * SC + cc0] = make_float2(acc[t][j][2], acc[t][j][3]);
        }
    __syncthreads();

    // ---- epilogue: thread -> (row, half) ----
    const int r = tid >> 1;
    const int hf = tid & 1;
    const int row = tile + r;
    if (row < M) {
        const float* tpr = nullptr;
        if (MODE == 1) tpr = tp + b_idx[row] * 256;
        #pragma unroll 4
        for (int q = 0; q < 16; ++q) {
            const int p0 = hf * 64 + q * 4;
            float v[4];
            #pragma unroll
            for (int i = 0; i < 4; ++i) v[i] = Cs[r * SC + p0 + i];
            float4 ad;
            if (MODE == 2) ad = *(const float4*)(addend + (size_t)row * NFW + p0);
            #pragma unroll
            for (int i = 0; i < 4; ++i) {
                if (MODE == 0) {
                    if (bias) v[i] += bias[p0 + i];
                    if (bias2) v[i] += bias2[p0 + i];
                } else if (MODE == 1) {
                    v[i] = (1.f + tpr[p0 + i]) * (v[i] + bias[p0 + i]) + tpr[128 + p0 + i];
                } else {
                    v[i] += (&ad.x)[i];
                }
            }
            *(float4*)(out + (size_t)row * NFW + p0) = make_float4(v[0], v[1], v[2], v[3]);
        }
    }
}

// ---------------- launch ----------------
extern "C" void kernel_launch(void* const* d_in, const int* in_sizes, int n_in,
                              void* d_out, int out_size) {
    const float* x        = (const float*)d_in[0];
    const float* t        = (const float*)d_in[1];
    const int*   b_idx    = (const int*)d_in[2];
    const int*   nbr      = (const int*)d_in[3];
    const int*   nbr_down = (const int*)d_in[4];
    const float* g1       = (const float*)d_in[5];
    const float* be1      = (const float*)d_in[6];
    const float* W1       = (const float*)d_in[7];
    const float* b1       = (const float*)d_in[8];
    const float* Wtm      = (const float*)d_in[9];
    const float* bt       = (const float*)d_in[10];
    const float* g2       = (const float*)d_in[11];
    const float* be2      = (const float*)d_in[12];
    const float* W2       = (const float*)d_in[13];
    const float* b2       = (const float*)d_in[14];
    const float* Wid      = (const float*)d_in[15];
    const float* bid      = (const float*)d_in[16];
    const float* Wd       = (const float*)d_in[17];
    float* out = (float*)d_out;

    float *ph, *ph2, *pstats, *ptp;
    __half *pa, *pwt;
    cudaGetSymbolAddress((void**)&pa, g_a);
    cudaGetSymbolAddress((void**)&ph, g_h);
    cudaGetSymbolAddress((void**)&ph2, g_h2);
    cudaGetSymbolAddress((void**)&pstats, g_stats);
    cudaGetSymbolAddress((void**)&ptp, g_tp);
    cudaGetSymbolAddress((void**)&pwt, g_wt);

    cudaFuncSetAttribute(conv_mma<64, 1, false>,
                         cudaFuncAttributeMaxDynamicSharedMemorySize, SMEM_BYTES);
    cudaFuncSetAttribute(conv_mma<64, 0, true>,
                         cudaFuncAttributeMaxDynamicSharedMemorySize, SMEM_BYTES);
    cudaFuncSetAttribute(conv_mma<128, 2, false>,
                         cudaFuncAttributeMaxDynamicSharedMemorySize, SMEM_BYTES);
    cudaFuncSetAttribute(conv_mma<128, 0, false>,
                         cudaFuncAttributeMaxDynamicSharedMemorySize, SMEM_BYTES);

    const int N = in_sizes[0] / 64;             // 200000
    const int K = in_sizes[3] / N;              // 27
    const int KD = in_sizes[17] / (128 * 128);  // 8
    const int ND = in_sizes[4] / KD;            // 25000
    const float invN = 1.f / (float)N;
    const int GN = (N + 127) / 128;
    const int GD = (ND + 127) / 128;
    __half* pxh = pa + (size_t)N * 64;          // f16-permuted x (second half of g_a)

    // Launch order: conv1 at launch #4 (the ncu-captured slot).
    // 1: W1 transpose (fragment-major) + zero stats + temb (16 tail blocks)
    transpose_w_kernel<<<232, 256>>>(W1, pwt + WT1_OFF, K, 64, pstats, t, Wtm, bt, ptp, 16);
    // 2: BN1 stats
    stats_kernel<64><<<512, 256>>>(x, N, pstats + 0, pstats + 64);
    // 3: bnsilu1 (fused finalize) -> g_a[0:N*64]
    bnsilu_kernel<64><<<2048, 256>>>(x, pstats + 0, pstats + 64, g1, be1, invN,
                                     (size_t)N * 64, pa);
    // 4: conv1 (64->128) + b1 + TE affine -> g_h   << ncu capture slot
    conv_mma<64, 1, false><<<GN, CTHREADS, SMEM_BYTES>>>(
        pa, nbr, K, N, pwt + WT1_OFF, b1, nullptr, ph, nullptr, ptp, b_idx);

    // 5: x -> f16 permuted (for idconv)
    tohalf_kernel<<<2048, 256>>>(x, (size_t)N * 64, pxh);
    // 6: W2 transpose
    transpose_w_kernel<<<432, 256>>>(W2, pwt + WT2_OFF, K, 128, nullptr,
                                     nullptr, nullptr, nullptr, nullptr, 0);
    // 7: BN2 stats
    stats_kernel<128><<<512, 256>>>(ph, N, pstats + 128, pstats + 256);
    // 8: Wid transpose
    transpose_w_kernel<<<32, 256>>>(Wid, pwt + WTID_OFF, 1, 64, nullptr,
                                    nullptr, nullptr, nullptr, nullptr, 0);
    // 9: idconv: h2 = x @ Wid + bid + b2
    conv_mma<64, 0, true><<<GN, CTHREADS, SMEM_BYTES>>>(
        pxh, nullptr, 1, N, pwt + WTID_OFF, bid, b2, ph2, nullptr, nullptr, nullptr);
    // 10: bnsilu2 (fused finalize) -> g_a (full N*128)
    bnsilu_kernel<128><<<2048, 256>>>(ph, pstats + 128, pstats + 256, g2, be2, invN,
                                      (size_t)N * 128, pa);
    // 11: conv2 (128->128) + h2 addend -> g_h2
    conv_mma<128, 2, false><<<GN, CTHREADS, SMEM_BYTES>>>(
        pa, nbr, K, N, pwt + WT2_OFF, nullptr, nullptr, ph2, ph2, nullptr, nullptr);
    // 12: Wd transpose
    transpose_w_kernel<<<128, 256>>>(Wd, pwt + WTD_OFF, KD, 128, nullptr,
                                     nullptr, nullptr, nullptr, nullptr, 0);
    // 13: h2 -> f16 permuted
    tohalf_kernel<<<2048, 256>>>(ph2, (size_t)N * 128, pa);
    // 14: strided down conv (8 taps) -> out [ND, 128]
    conv_mma<128, 0, false><<<GD, CTHREADS, SMEM_BYTES>>>(
        pa, nbr_down, KD, ND, pwt + WTD_OFF, nullptr, nullptr, out,
        nullptr, nullptr, nullptr);
}

// round 16
// speedup vs baseline: 1.4674x; 1.0551x over previous
#include <cuda_runtime.h>
#include <cuda_fp16.h>
#include <cstdint>

#define N_VOX 200000
#define NFW 128
#define SC 136                       // C staging row stride (floats)
#define SMEM_BYTES (128 * SC * 4)    // 69632 B (epilogue staging only)
#define CTHREADS 256                 // 8 warps: 4m x 2n of m32 x n64; 2 CTAs/SM

// ---------------- scratch (static device globals; no allocation) ----------------
__device__ __half g_a[(size_t)N_VOX * 128];  // f16 k-permuted activations
__device__ __half g_xh[(size_t)N_VOX * 64];  // f16 k-permuted x (for fused idconv)
__device__ float g_h[(size_t)N_VOX * 128];   // conv1 output h (f32 natural)
__device__ float g_h2[(size_t)N_VOX * 128];  // conv2+idconv output (f32 natural)
__device__ float g_stats[384];
__device__ float g_tp[16 * 256];
__device__ __half g_wt[802816];              // fragment-major f16 weights

#define WT1_OFF 0
#define WT2_OFF (27 * 128 * 64)
#define WTD_OFF (WT2_OFF + 27 * 128 * 128)
#define WTID_OFF (WTD_OFF + 8 * 128 * 128)

// A permutation within each 64-half chunk: for group-pair gp (groups 2gp,2gp+1),
// lane lp owns one 16B run at pos = gp*32 + lp*8 -> one LDG.128 = 2 groups' a-frags.
// W fragment-major superblocks of 256 halves: per (k,ch), sb = jg*2+gp;
// within: off = lane*8 + gg*4 + slot.

// ---------------- helpers ----------------
__device__ __forceinline__ float silu_(float z) {
    return z * (1.f / (1.f + __expf(-z)));
}
__device__ __forceinline__ void mma16(float* c, const uint32_t* a, uint32_t b0, uint32_t b1) {
    asm volatile(
        "mma.sync.aligned.m16n8k16.row.col.f32.f16.f16.f32 "
        "{%0,%1,%2,%3}, {%4,%5,%6,%7}, {%8,%9}, {%0,%1,%2,%3};"
        : "+f"(c[0]), "+f"(c[1]), "+f"(c[2]), "+f"(c[3])
        : "r"(a[0]), "r"(a[1]), "r"(a[2]), "r"(a[3]), "r"(b0), "r"(b1));
}
__device__ __forceinline__ int permpos64(int c6) {
    int g = c6 >> 4, h = c6 & 15;
    int lp = (h >> 1) & 3, hi = h >> 3, e = h & 1;
    return ((g >> 1) << 5) | (lp << 3) | ((g & 1) << 2) | (hi << 1) | e;
}

// ---------------- small kernels ----------------
template <int C>
__global__ void stats_kernel(const float* __restrict__ X, int M,
                             float* __restrict__ gsum, float* __restrict__ gsq) {
    constexpr int RPB = 256 / C;
    const int c = threadIdx.x & (C - 1);
    const int rg = threadIdx.x / C;
    float s = 0.f, q = 0.f;
    for (int r = blockIdx.x * RPB + rg; r < M; r += gridDim.x * RPB) {
        float v = X[(size_t)r * C + c];
        s += v;
        q += v * v;
    }
    __shared__ float sh[256];
    __shared__ float sh2[256];
    sh[threadIdx.x] = s;
    sh2[threadIdx.x] = q;
    __syncthreads();
    if (threadIdx.x < C) {
        #pragma unroll
        for (int g = 1; g < RPB; ++g) {
            s += sh[g * C + c];
            q += sh2[g * C + c];
        }
        atomicAdd(&gsum[c], s);
        atomicAdd(&gsq[c], q);
    }
}

// bnsilu with fused BN-finalize; output f16 k-permuted (64-half chunks)
template <int C>
__global__ void bnsilu_kernel(const float* __restrict__ X,
                              const float* __restrict__ gsum, const float* __restrict__ gsq,
                              const float* __restrict__ g, const float* __restrict__ be,
                              float invM, size_t total, __half* __restrict__ out) {
    __shared__ float ssc[C], sbi[C];
    if (threadIdx.x < C) {
        int c = threadIdx.x;
        float m = gsum[c] * invM;
        float v = gsq[c] * invM - m * m;
        float a = g[c] * rsqrtf(v + 1e-5f);
        ssc[c] = a;
        sbi[c] = be[c] - m * a;
    }
    __syncthreads();
    for (size_t i = (size_t)blockIdx.x * blockDim.x + threadIdx.x; i < total;
         i += (size_t)gridDim.x * blockDim.x) {
        int c = (int)(i & (size_t)(C - 1));
        float z = X[i] * ssc[c] + sbi[c];
        int pos = permpos64((int)(i & 63));
        out[(i & ~(size_t)63) | (size_t)pos] = __float2half_rn(silu_(z));
    }
}

// f32 natural -> f16 k-permuted (64-half chunks)
__global__ void tohalf_kernel(const float* __restrict__ X, size_t total,
                              __half* __restrict__ out) {
    for (size_t i = (size_t)blockIdx.x * blockDim.x + threadIdx.x; i < total;
         i += (size_t)gridDim.x * blockDim.x) {
        int pos = permpos64((int)(i & 63));
        out[(i & ~(size_t)63) | (size_t)pos] = __float2half_rn(X[i]);
    }
}

// W[k][c][n] -> fragment-major superblocks. block 0 zeroes stats; tail blocks temb.
__global__ void transpose_w_kernel(const float* __restrict__ W, __half* __restrict__ Wt,
                                   int K, int CIN, float* stats_zero,
                                   const float* __restrict__ t, const float* __restrict__ Wtm,
                                   const float* __restrict__ bt, float* __restrict__ tp,
                                   int ntb) {
    if (ntb > 0 && (int)blockIdx.x >= (int)gridDim.x - ntb) {
        __shared__ float st[256];
        const int b = blockIdx.x - (gridDim.x - ntb);
        const int j = threadIdx.x;
        st[j] = silu_(t[b * 256 + j]);
        __syncthreads();
        float acc = bt[j];
        #pragma unroll 8
        for (int e = 0; e < 256; ++e) acc += st[e] * Wtm[e * 256 + j];
        tp[b * 256 + j] = acc;
        return;
    }
    if (stats_zero && blockIdx.x == 0) {
        for (int z = threadIdx.x; z < 384; z += blockDim.x) stats_zero[z] = 0.f;
    }
    const int nwb = gridDim.x - ntb;
    const int hpk = CIN * 128;          // halves per k
    const int total = K * hpk;
    for (int i = blockIdx.x * blockDim.x + threadIdx.x; i < total;
         i += nwb * blockDim.x) {
        int k = i / hpk;
        int rem = i - k * hpk;
        int sblk = rem >> 8;            // 256-half superblocks
        int off = rem & 255;
        int ch = sblk >> 5;             // superblock / 32
        int sb = sblk & 31;
        int jg = sb >> 1, gp = sb & 1;
        int lane = off >> 3, gg = (off >> 2) & 1, slot = off & 3;
        int lr = lane >> 2, lp = lane & 3;
        int g = gp * 2 + gg;
        int hi = slot >> 1, e = slot & 1;
        int c = (ch << 6) | (g << 4) | (2 * lp + 8 * hi + e);
        int n = (jg << 3) | lr;
        Wt[i] = __float2half_rn(W[(k * CIN + c) * 128 + n]);
    }
}

// ---------------- direct-LDG.128 f16 m16n8k16 gathered sparse-conv GEMM ----------------
// 128-row x 128-col tile, 256 threads (8 warps = 4m x 2n of m32 x n64), f32 accum,
// 2 CTAs/SM. nbr loaded once per k (shared over NCH chunks). Optional fused identity
// chunk (FUSEID): adds Aid[row] @ Wtid into the accumulator (replaces idconv kernel).
// MODE 0: + bias (+bias2); MODE 1: TE affine
template <int CIN, int MODE, bool FUSEID>
__global__ void __launch_bounds__(CTHREADS, 2)
conv_mma(const __half* __restrict__ Af, const int* __restrict__ nbr, int K, int M,
         const __half* __restrict__ Wt,
         const float* __restrict__ bias, const float* __restrict__ bias2,
         float* __restrict__ out,
         const __half* __restrict__ Aid, const __half* __restrict__ Wtid,
         const float* __restrict__ tp, const int* __restrict__ b_idx) {
    extern __shared__ float Cs[];

    const int tid = threadIdx.x;
    const int wid = tid >> 5, lane = tid & 31;
    const int wr = wid & 3, wc = wid >> 2;   // m0=32*wr, n0=64*wc
    const int lr = lane >> 2, lp = lane & 3;
    const int tile = blockIdx.x * 128;

    constexpr int NCH = CIN / 64;

    float acc[2][8][4];
    #pragma unroll
    for (int t = 0; t < 2; ++t)
        #pragma unroll
        for (int j = 0; j < 8; ++j)
            #pragma unroll
            for (int i = 0; i < 4; ++i) acc[t][j][i] = 0.f;

    const int rbase = tile + 32 * wr + lr;

    auto run_chunk = [&](const __half* const* aq, const int* idxs, const __half* wb) {
        #pragma unroll
        for (int gp = 0; gp < 2; ++gp) {
            uint4 al[4];
            #pragma unroll
            for (int q = 0; q < 4; ++q) {
                uint4 v = make_uint4(0u, 0u, 0u, 0u);
                if (idxs[q] >= 0) v = *(const uint4*)(aq[q] + gp * 32);
                al[q] = v;
            }
            uint32_t a0[2][4], a1[2][4];
            #pragma unroll
            for (int t = 0; t < 2; ++t) {
                a0[t][0] = al[2 * t].x;     a0[t][1] = al[2 * t + 1].x;
                a0[t][2] = al[2 * t].y;     a0[t][3] = al[2 * t + 1].y;
                a1[t][0] = al[2 * t].z;     a1[t][1] = al[2 * t + 1].z;
                a1[t][2] = al[2 * t].w;     a1[t][3] = al[2 * t + 1].w;
            }
            #pragma unroll
            for (int j = 0; j < 8; ++j) {
                uint4 b = *(const uint4*)(wb + (size_t)(j * 2 + gp) * 256);
                mma16(acc[0][j], a0[0], b.x, b.y);
                mma16(acc[1][j], a0[1], b.x, b.y);
                mma16(acc[0][j], a1[0], b.z, b.w);
                mma16(acc[1][j], a1[1], b.z, b.w);
            }
        }
    };

    for (int k = 0; k < K; ++k) {
        int idxs[4];
        #pragma unroll
        for (int q = 0; q < 4; ++q) {
            int row = rbase + 8 * q;
            idxs[q] = (row < M) ? __ldg(nbr + (size_t)k * M + row) : -1;
        }
        #pragma unroll
        for (int ch = 0; ch < NCH; ++ch) {
            const __half* aq[4];
            #pragma unroll
            for (int q = 0; q < 4; ++q)
                aq[q] = Af + (size_t)(idxs[q] < 0 ? 0 : idxs[q]) * CIN + ch * 64 + lp * 8;
            const __half* wb = Wt + ((size_t)(k * NCH + ch) * 32 + (size_t)wc * 16) * 256
                                  + lane * 8;
            run_chunk(aq, idxs, wb);
        }
    }

    if (FUSEID) {
        // fused identity conv chunk: Aid [M,64] f16-permuted, Wtid 1-k fragment blocks
        int idxs[4];
        const __half* aq[4];
        #pragma unroll
        for (int q = 0; q < 4; ++q) {
            int row = rbase + 8 * q;
            idxs[q] = (row < M) ? row : -1;
            aq[q] = Aid + (size_t)(idxs[q] < 0 ? 0 : idxs[q]) * 64 + lp * 8;
        }
        const __half* wb = Wtid + (size_t)wc * 16 * 256 + lane * 8;
        run_chunk(aq, idxs, wb);
    }

    // ---- stage C through smem for coalesced stores ----
    __syncthreads();
    #pragma unroll
    for (int t = 0; t < 2; ++t)
        #pragma unroll
        for (int j = 0; j < 8; ++j) {
            int r0 = 32 * wr + 16 * t + lr;
            int cc0 = 64 * wc + 8 * j + 2 * lp;
            *(float2*)&Cs[r0 * SC + cc0] = make_float2(acc[t][j][0], acc[t][j][1]);
            *(float2*)&Cs[(r0 + 8) * SC + cc0] = make_float2(acc[t][j][2], acc[t][j][3]);
        }
    __syncthreads();

    // ---- epilogue: thread -> (row, half) ----
    const int r = tid >> 1;
    const int hf = tid & 1;
    const int row = tile + r;
    if (row < M) {
        const float* tpr = nullptr;
        if (MODE == 1) tpr = tp + b_idx[row] * 256;
        #pragma unroll 4
        for (int q = 0; q < 16; ++q) {
            const int p0 = hf * 64 + q * 4;
            float v[4];
            #pragma unroll
            for (int i = 0; i < 4; ++i) v[i] = Cs[r * SC + p0 + i];
            #pragma unroll
            for (int i = 0; i < 4; ++i) {
                if (MODE == 0) {
                    if (bias) v[i] += bias[p0 + i];
                    if (bias2) v[i] += bias2[p0 + i];
                } else {
                    v[i] = (1.f + tpr[p0 + i]) * (v[i] + bias[p0 + i]) + tpr[128 + p0 + i];
                }
            }
            *(float4*)(out + (size_t)row * NFW + p0) = make_float4(v[0], v[1], v[2], v[3]);
        }
    }
}

// ---------------- launch ----------------
extern "C" void kernel_launch(void* const* d_in, const int* in_sizes, int n_in,
                              void* d_out, int out_size) {
    const float* x        = (const float*)d_in[0];
    const float* t        = (const float*)d_in[1];
    const int*   b_idx    = (const int*)d_in[2];
    const int*   nbr      = (const int*)d_in[3];
    const int*   nbr_down = (const int*)d_in[4];
    const float* g1       = (const float*)d_in[5];
    const float* be1      = (const float*)d_in[6];
    const float* W1       = (const float*)d_in[7];
    const float* b1       = (const float*)d_in[8];
    const float* Wtm      = (const float*)d_in[9];
    const float* bt       = (const float*)d_in[10];
    const float* g2       = (const float*)d_in[11];
    const float* be2      = (const float*)d_in[12];
    const float* W2       = (const float*)d_in[13];
    const float* b2       = (const float*)d_in[14];
    const float* Wid      = (const float*)d_in[15];
    const float* bid      = (const float*)d_in[16];
    const float* Wd       = (const float*)d_in[17];
    float* out = (float*)d_out;

    float *ph, *ph2, *pstats, *ptp;
    __half *pa, *pxh, *pwt;
    cudaGetSymbolAddress((void**)&pa, g_a);
    cudaGetSymbolAddress((void**)&pxh, g_xh);
    cudaGetSymbolAddress((void**)&ph, g_h);
    cudaGetSymbolAddress((void**)&ph2, g_h2);
    cudaGetSymbolAddress((void**)&pstats, g_stats);
    cudaGetSymbolAddress((void**)&ptp, g_tp);
    cudaGetSymbolAddress((void**)&pwt, g_wt);

    cudaFuncSetAttribute(conv_mma<64, 1, false>,
                         cudaFuncAttributeMaxDynamicSharedMemorySize, SMEM_BYTES);
    cudaFuncSetAttribute(conv_mma<128, 0, true>,
                         cudaFuncAttributeMaxDynamicSharedMemorySize, SMEM_BYTES);
    cudaFuncSetAttribute(conv_mma<128, 0, false>,
                         cudaFuncAttributeMaxDynamicSharedMemorySize, SMEM_BYTES);

    const int N = in_sizes[0] / 64;             // 200000
    const int K = in_sizes[3] / N;              // 27
    const int KD = in_sizes[17] / (128 * 128);  // 8
    const int ND = in_sizes[4] / KD;            // 25000
    const float invN = 1.f / (float)N;
    const int GN = (N + 127) / 128;
    const int GD = (ND + 127) / 128;

    // Launch order: conv1 at launch #4 (the ncu-captured slot).
    // 1: W1 transpose (fragment-major) + zero stats + temb (16 tail blocks)
    transpose_w_kernel<<<232, 256>>>(W1, pwt + WT1_OFF, K, 64, pstats, t, Wtm, bt, ptp, 16);
    // 2: BN1 stats
    stats_kernel<64><<<512, 256>>>(x, N, pstats + 0, pstats + 64);
    // 3: bnsilu1 (fused finalize) -> g_a[0:N*64]
    bnsilu_kernel<64><<<2048, 256>>>(x, pstats + 0, pstats + 64, g1, be1, invN,
                                     (size_t)N * 64, pa);
    // 4: conv1 (64->128) + b1 + TE affine -> g_h   << ncu capture slot
    conv_mma<64, 1, false><<<GN, CTHREADS, SMEM_BYTES>>>(
        pa, nbr, K, N, pwt + WT1_OFF, b1, nullptr, ph, nullptr, nullptr, ptp, b_idx);

    // 5: x -> f16 permuted (for fused idconv)
    tohalf_kernel<<<2048, 256>>>(x, (size_t)N * 64, pxh);
    // 6: W2 transpose
    transpose_w_kernel<<<432, 256>>>(W2, pwt + WT2_OFF, K, 128, nullptr,
                                     nullptr, nullptr, nullptr, nullptr, 0);
    // 7: BN2 stats
    stats_kernel<128><<<512, 256>>>(ph, N, pstats + 128, pstats + 256);
    // 8: Wid transpose
    transpose_w_kernel<<<32, 256>>>(Wid, pwt + WTID_OFF, 1, 64, nullptr,
                                    nullptr, nullptr, nullptr, nullptr, 0);
    // 9: bnsilu2 (fused finalize) -> g_a (full N*128)
    bnsilu_kernel<128><<<2048, 256>>>(ph, pstats + 128, pstats + 256, g2, be2, invN,
                                      (size_t)N * 128, pa);
    // 10: conv2 (128->128) + fused idconv chunk + b2 + bid -> g_h2
    conv_mma<128, 0, true><<<GN, CTHREADS, SMEM_BYTES>>>(
        pa, nbr, K, N, pwt + WT2_OFF, b2, bid, ph2, pxh, pwt + WTID_OFF, nullptr, nullptr);
    // 11: Wd transpose
    transpose_w_kernel<<<128, 256>>>(Wd, pwt + WTD_OFF, KD, 128, nullptr,
                                     nullptr, nullptr, nullptr, nullptr, 0);
    // 12: h2 -> f16 permuted
    tohalf_kernel<<<2048, 256>>>(ph2, (size_t)N * 128, pa);
    // 13: strided down conv (8 taps) -> out [ND, 128]
    conv_mma<128, 0, false><<<GD, CTHREADS, SMEM_BYTES>>>(
        pa, nbr_down, KD, ND, pwt + WTD_OFF, nullptr, nullptr, out,
        nullptr, nullptr, nullptr, nullptr);
}